// round 15
// baseline (speedup 1.0000x reference)
#include <cuda_runtime.h>
#include <cuda_fp16.h>
#include <math.h>

#define BB   4096
#define NN   32
#define DA   16
#define DOBS 64
#define HH   256
#define BN   (BB*NN)
#define ROWS 64
#define NT   256
#define LDA  144
#define LN32 3.4657359027997265f
#define LR   0.1f

// ---------------- device scratch ----------------
__device__ float    g_pre1[BN*HH];     // fragment-contiguous, pre-biased with b1
__device__ unsigned g_w2pf [8*4096];
__device__ unsigned g_w2tpf[8*4096];
__device__ unsigned g_w1pf [2*4096];
__device__ unsigned g_w1apf[  4096];
__device__ unsigned g_w1atpf[ 2048];

// ---------------- helpers ----------------
__device__ __forceinline__ unsigned pk(float lo, float hi){
    __half2 h = __floats2half2_rn(lo, hi);
    return *reinterpret_cast<unsigned*>(&h);
}
__device__ __forceinline__ void mma8h(float* c, const unsigned* a, unsigned b0, unsigned b1){
    asm volatile("mma.sync.aligned.m16n8k16.row.col.f32.f16.f16.f32 "
                 "{%0,%1,%2,%3},{%4,%5,%6,%7},{%8,%9},{%0,%1,%2,%3};\n"
                 : "+f"(c[0]),"+f"(c[1]),"+f"(c[2]),"+f"(c[3])
                 : "r"(a[0]),"r"(a[1]),"r"(a[2]),"r"(a[3]),"r"(b0),"r"(b1));
}
__device__ __forceinline__ int fslot(int n){
    return ((n>>5)<<4) | (((n>>1)&3)<<2) | ((n>>3)&1) | (((n>>4)&1)<<1);
}
__device__ __forceinline__ void preloadB(uint4 B[4], const unsigned* __restrict__ img,
                                         int wn, int g, int sw, int h){
#pragma unroll
    for (int ni=0;ni<4;ni++){
        int n = wn*64 + (h*4+ni)*8 + g;
        B[ni] = __ldg((const uint4*)&img[n*16 + sw]);
    }
}
// pipelined 256-K phase; dependent mma pairs separated by 8 instructions
__device__ __forceinline__ void phase256(float acc[2][8][4], const unsigned* A, int lda,
                                         const unsigned* __restrict__ img, uint4 B[4],
                                         int wm, int wn, int g, int tg)
{
    const int sw = ((tg ^ (g&3))<<2);
    const int r0 = wm*32 + g;
    unsigned a0k0[4], a0k1[4], a1k0[4], a1k1[4];
#pragma unroll
    for (int step=0; step<16; step++){
        const int c = step>>1, h = step&1;
        uint4 Bn[4];
        if (step<15)
            preloadB(Bn, img + ((step+1)>>1)*4096, wn, g, sw, (step+1)&1);
        if (h==0){
            const int ab = c*16 + tg*4;
            uint4 A0 = *(const uint4*)&A[(r0   )*lda + ab];
            uint4 A8 = *(const uint4*)&A[(r0+ 8)*lda + ab];
            uint4 A16= *(const uint4*)&A[(r0+16)*lda + ab];
            uint4 A24= *(const uint4*)&A[(r0+24)*lda + ab];
            a0k0[0]=A0.x; a0k0[1]=A8.x; a0k0[2]=A0.y; a0k0[3]=A8.y;
            a0k1[0]=A0.z; a0k1[1]=A8.z; a0k1[2]=A0.w; a0k1[3]=A8.w;
            a1k0[0]=A16.x; a1k0[1]=A24.x; a1k0[2]=A16.y; a1k0[3]=A24.y;
            a1k1[0]=A16.z; a1k1[1]=A24.z; a1k1[2]=A16.w; a1k1[3]=A24.w;
        }
        // all k0 first, then all k1 (per-acc order unchanged: k0 then k1)
#pragma unroll
        for (int ni=0;ni<4;ni++) mma8h(acc[0][h*4+ni], a0k0, B[ni].x, B[ni].y);
#pragma unroll
        for (int ni=0;ni<4;ni++) mma8h(acc[1][h*4+ni], a1k0, B[ni].x, B[ni].y);
#pragma unroll
        for (int ni=0;ni<4;ni++) mma8h(acc[0][h*4+ni], a0k1, B[ni].z, B[ni].w);
#pragma unroll
        for (int ni=0;ni<4;ni++) mma8h(acc[1][h*4+ni], a1k1, B[ni].z, B[ni].w);
        if (step<15){
#pragma unroll
            for (int ni=0;ni<4;ni++) B[ni]=Bn[ni];
        }
    }
}
__device__ __forceinline__ void mma_32k(float acc[2][8][4], const unsigned* A, int lda, int c,
                                        const unsigned* __restrict__ gslab, int wm, int wn, int g, int tg)
{
    const int r0 = wm*32 + g;
    const int ab = c*16 + tg*4;
    uint4 A0 = *(const uint4*)&A[(r0   )*lda + ab];
    uint4 A8 = *(const uint4*)&A[(r0+ 8)*lda + ab];
    uint4 A16= *(const uint4*)&A[(r0+16)*lda + ab];
    uint4 A24= *(const uint4*)&A[(r0+24)*lda + ab];
    unsigned a0k0[4] = {A0.x, A8.x, A0.y, A8.y};
    unsigned a0k1[4] = {A0.z, A8.z, A0.w, A8.w};
    unsigned a1k0[4] = {A16.x, A24.x, A16.y, A24.y};
    unsigned a1k1[4] = {A16.z, A24.z, A16.w, A24.w};
    const int sw = ((tg ^ (g&3))<<2);
    uint4 B[8];
#pragma unroll
    for (int ni=0;ni<8;ni++){
        int n = wn*64 + ni*8 + g;
        B[ni] = __ldg((const uint4*)&gslab[n*16 + sw]);
    }
#pragma unroll
    for (int ni=0;ni<8;ni++) mma8h(acc[0][ni], a0k0, B[ni].x, B[ni].y);
#pragma unroll
    for (int ni=0;ni<8;ni++) mma8h(acc[1][ni], a1k0, B[ni].x, B[ni].y);
#pragma unroll
    for (int ni=0;ni<8;ni++) mma8h(acc[0][ni], a0k1, B[ni].z, B[ni].w);
#pragma unroll
    for (int ni=0;ni<8;ni++) mma8h(acc[1][ni], a1k1, B[ni].z, B[ni].w);
}

// ---------------- one-time weight packing ----------------
__global__ void pack_weights(const float* __restrict__ w1, const float* __restrict__ w2)
{
    int idx = blockIdx.x * 512 + threadIdx.x;
    if (idx < 32768){
        int c = idx>>12, off = idx&4095, n = off>>4, rem = off&15;
        int tg = (rem>>2) ^ (n&3), j = rem&3;
        int k0 = c*32 + 2*tg + (j&1)*8 + ((j>>1)&1)*16;
        g_w2pf[idx] = pk(w2[(size_t)k0*HH+n], w2[(size_t)(k0+1)*HH+n]);
    } else if (idx < 65536){
        int t = idx-32768;
        int c = t>>12, off = t&4095, n = off>>4, rem = off&15;
        int tg = (rem>>2) ^ (n&3), j = rem&3;
        int k0 = c*32 + 2*tg + (j&1)*8 + ((j>>1)&1)*16;
        g_w2tpf[t] = pk(w2[(size_t)n*HH+k0], w2[(size_t)n*HH+k0+1]);
    } else if (idx < 73728){
        int t = idx-65536;
        int c = t>>12, off = t&4095, n = off>>4, rem = off&15;
        int tg = (rem>>2) ^ (n&3), j = rem&3;
        int k0 = c*32 + 2*tg + (j&1)*8 + ((j>>1)&1)*16;
        g_w1pf[t] = pk(w1[(size_t)k0*HH+n], w1[(size_t)(k0+1)*HH+n]);
    } else if (idx < 77824){
        int t = idx-73728;
        int n = t>>4, rem = t&15;
        int tg = (rem>>2) ^ (n&3), j = rem&3;
        int k0 = 2*tg + (j&1)*8 + ((j>>1)&1)*16;
        g_w1apf[t] = (k0 < 16) ? pk(w1[(size_t)(DOBS+k0)*HH+n], w1[(size_t)(DOBS+k0+1)*HH+n]) : 0u;
    } else if (idx < 79872){
        int t = idx-77824;
        int c = t>>8, r = t&255, n = r>>4, rem = r&15;
        int tg = (rem>>2) ^ (n&3), j = rem&3;
        int k0 = c*32 + 2*tg + (j&1)*8 + ((j>>1)&1)*16;
        g_w1atpf[t] = pk(w1[(size_t)(DOBS+n)*HH+k0], w1[(size_t)(DOBS+n)*HH+k0+1]);
    }
}

// ---------------- pre1 = obs @ W1[0:64,:] + b1 ----------------
#define PRE1_SMEM ((2304 + 256) * 4)
__global__ void __launch_bounds__(NT) pre1_kernel(const float* __restrict__ obs,
                                                  const float* __restrict__ b1)
{
    extern __shared__ unsigned smu[];
    unsigned* obs_s = smu;
    float*    b1s   = (float*)(smu + 2304);
    const int tid = threadIdx.x;
    const int lane = tid & 31, wid = tid >> 5;
    const int g = lane >> 2, tg = lane & 3;
    const int wm = wid >> 2, wn = wid & 3;
    const int row0 = blockIdx.x * ROWS;

    b1s[tid] = b1[tid];
#pragma unroll
    for (int i=0;i<8;i++){
        int lin = i*NT + tid; int r = lin>>5, s = lin&31;
        int c = s>>4, rem = s&15, t = rem>>2, j = rem&3;
        int k0 = c*32 + 2*t + (j&1)*8 + ((j>>1)&1)*16;
        const float* orow = &obs[(size_t)(row0 + r)*DOBS];
        obs_s[r*36 + s] = pk(orow[k0], orow[k0+1]);
    }
    __syncthreads();

    float acc[2][8][4];
#pragma unroll
    for (int mi=0;mi<2;mi++)
#pragma unroll
        for (int ni=0;ni<8;ni++)
#pragma unroll
            for (int j=0;j<4;j++) acc[mi][ni][j]=0.f;
#pragma unroll
    for (int s=0;s<2;s++)
        mma_32k(acc, obs_s, 36, s, g_w1pf + s*4096, wm, wn, g, tg);

    float4* pp = (float4*)(g_pre1 + ((size_t)blockIdx.x*NT + tid)*64);
#pragma unroll
    for (int mi=0;mi<2;mi++)
#pragma unroll
        for (int ni=0;ni<8;ni++){
            int n = wn*64 + ni*8 + 2*tg;
            pp[mi*8+ni] = make_float4(acc[mi][ni][0]+b1s[n], acc[mi][ni][1]+b1s[n+1],
                                      acc[mi][ni][2]+b1s[n], acc[mi][ni][3]+b1s[n+1]);
        }
}

// ---------------- fused 3-step MLP + SVGD ----------------
#define OFF_H1   0
#define OFF_AUX  9216
#define OFF_SS   11264
#define OFF_QP   12288
#define OFF_XS   12544
#define OFF_LGP  13568
#define OFF_PB2  13824
#define OFF_W3R  14080
#define OFF_W3T  14336
#define OFF_HIST 14592
#define MLP_SMEM (15712*4)

__global__ void __launch_bounds__(NT,2) mlp_kernel(
    const float* __restrict__ a_in, const float* __restrict__ b2,
    const float* __restrict__ w3, const float* __restrict__ b3,
    float* __restrict__ q_out, float* __restrict__ out_a, float* __restrict__ out_logp)
{
    extern __shared__ unsigned smu[];
    unsigned* sh1u = smu + OFF_H1;
    unsigned* asu  = smu + OFF_AUX;
    float*    spf  = (float*)(smu + OFF_AUX);
    float*    Ss   = (float*)(smu + OFF_SS);
    float*    qps  = (float*)(smu + OFF_QP);
    float*    Xs   = (float*)(smu + OFF_XS);
    float*    lgp  = (float*)(smu + OFF_LGP);
    float*    b2s  = (float*)(smu + OFF_PB2);
    float*    w3r  = (float*)(smu + OFF_W3R);
    unsigned* w3t  = smu + OFF_W3T;
    unsigned* hst  = smu + OFF_HIST;                 // 2 bufs x (2 bsub x 256)
    unsigned* wcle = smu + OFF_HIST + 1024;
    unsigned* wmin = smu + OFF_HIST + 1032;
    float*    gam  = (float*)(smu + OFF_HIST + 1040);

    const int tid = threadIdx.x;
    const int lane = tid & 31, wid = tid >> 5;
    const int g = lane >> 2, tg = lane & 3;
    const int wm = wid >> 2, wn = wid & 3;
    const int sw = ((tg ^ (g&3))<<2);
    const int row0 = blockIdx.x * ROWS;

    // ---- stage once ----
    {
        float4 av = *(const float4*)&a_in[(size_t)row0*DA + tid*4];
        *(float4*)&Xs[tid*4] = av;
        b2s[tid] = b2[tid];
        float v = w3[tid]; w3r[tid] = v;
        w3t[tid] = (unsigned)__half_as_ushort(__float2half_rn(v));
        if (tid < ROWS) lgp[tid] = 0.f;
    }
    __syncthreads();

#pragma unroll 1
    for (int step = 0; step < 3; step++){

    float acc[2][8][4];
    // ---- pre1 load hoisted above the pack (global, no smem dependence) ----
    {
        const float4* pp = (const float4*)(g_pre1 + ((size_t)blockIdx.x*NT + tid)*64);
#pragma unroll
        for (int mi=0;mi<2;mi++)
#pragma unroll
            for (int ni=0;ni<8;ni++){
                float4 v = pp[mi*8+ni];
                acc[mi][ni][0]=v.x; acc[mi][ni][1]=v.y; acc[mi][ni][2]=v.z; acc[mi][ni][3]=v.w;
            }
    }

    // pack actions fp16 pairs
#pragma unroll
    for (int i=0;i<4;i++){
        int lin = i*NT + tid; int r = lin>>4, s = lin&15;
        int t = s>>2, j = s&3;
        unsigned v = 0u;
        if (j < 2){
            int k0 = 2*t + (j&1)*8;
            v = pk(Xs[r*DA + k0], Xs[r*DA + k0 + 1]);
        }
        asu[r*16 + s] = v;
    }
    __syncthreads();

    // ---- Phase A: h1 = relu(pre1b + a@W1a) ----
    mma_32k(acc, asu, 16, 0, g_w1apf, wm, wn, g, tg);
    unsigned long long mbits = 0ull;
    {
#pragma unroll
        for (int mi=0;mi<2;mi++)
#pragma unroll
            for (int m2=0;m2<4;m2++){
                int niE = 2*m2, niO = niE+1;
                int nE = wn*64 + niE*8 + 2*tg;
                int r0 = wm*32 + mi*16 + g;
                int sl = fslot(nE);
                float p0 = acc[mi][niE][0];
                float p1 = acc[mi][niE][1];
                float p2 = acc[mi][niE][2];
                float p3 = acc[mi][niE][3];
                float q0 = acc[mi][niO][0];
                float q1 = acc[mi][niO][1];
                float q2 = acc[mi][niO][2];
                float q3 = acc[mi][niO][3];
                int bE = (mi*8+niE)*4, bO = (mi*8+niO)*4;
                mbits |= ((unsigned long long)(p0>0.f))<<(bE+0);
                mbits |= ((unsigned long long)(p1>0.f))<<(bE+1);
                mbits |= ((unsigned long long)(p2>0.f))<<(bE+2);
                mbits |= ((unsigned long long)(p3>0.f))<<(bE+3);
                mbits |= ((unsigned long long)(q0>0.f))<<(bO+0);
                mbits |= ((unsigned long long)(q1>0.f))<<(bO+1);
                mbits |= ((unsigned long long)(q2>0.f))<<(bO+2);
                mbits |= ((unsigned long long)(q3>0.f))<<(bO+3);
                *(uint2*)&sh1u[(r0  )*LDA + sl] =
                    make_uint2(pk(fmaxf(p0,0.f),fmaxf(p1,0.f)), pk(fmaxf(q0,0.f),fmaxf(q1,0.f)));
                *(uint2*)&sh1u[(r0+8)*LDA + sl] =
                    make_uint2(pk(fmaxf(p2,0.f),fmaxf(p3,0.f)), pk(fmaxf(q2,0.f),fmaxf(q3,0.f)));
            }
    }
    uint4 Bpre[4];
    preloadB(Bpre, g_w2pf, wn, g, sw, 0);
    __syncthreads();

    // ---- Phase B ----
#pragma unroll
    for (int mi=0;mi<2;mi++)
#pragma unroll
        for (int ni=0;ni<8;ni++)
#pragma unroll
            for (int j=0;j<4;j++) acc[mi][ni][j]=0.f;
    phase256(acc, sh1u, LDA, g_w2pf, Bpre, wm, wn, g, tg);
    __syncthreads();
    {
        float qp[2][2] = {{0.f,0.f},{0.f,0.f}};
#pragma unroll
        for (int mi=0;mi<2;mi++)
#pragma unroll
            for (int m2=0;m2<4;m2++){
                int niE = 2*m2, niO = niE+1;
                int nE = wn*64 + niE*8 + 2*tg;
                int nO = nE + 8;
                int r0 = wm*32 + mi*16 + g;
                int sl = fslot(nE);
                float p0 = acc[mi][niE][0] + b2s[nE];
                float p1 = acc[mi][niE][1] + b2s[nE+1];
                float p2 = acc[mi][niE][2] + b2s[nE];
                float p3 = acc[mi][niE][3] + b2s[nE+1];
                float q0 = acc[mi][niO][0] + b2s[nO];
                float q1 = acc[mi][niO][1] + b2s[nO+1];
                float q2 = acc[mi][niO][2] + b2s[nO];
                float q3 = acc[mi][niO][3] + b2s[nO+1];
                qp[mi][0] += fmaxf(p0,0.f)*w3r[nE] + fmaxf(p1,0.f)*w3r[nE+1]
                           + fmaxf(q0,0.f)*w3r[nO] + fmaxf(q1,0.f)*w3r[nO+1];
                qp[mi][1] += fmaxf(p2,0.f)*w3r[nE] + fmaxf(p3,0.f)*w3r[nE+1]
                           + fmaxf(q2,0.f)*w3r[nO] + fmaxf(q3,0.f)*w3r[nO+1];
                unsigned e0 = ((p0>0.f)?w3t[nE]:0u) | (((p1>0.f)?w3t[nE+1]:0u)<<16);
                unsigned o0 = ((q0>0.f)?w3t[nO]:0u) | (((q1>0.f)?w3t[nO+1]:0u)<<16);
                unsigned e1 = ((p2>0.f)?w3t[nE]:0u) | (((p3>0.f)?w3t[nE+1]:0u)<<16);
                unsigned o1 = ((q2>0.f)?w3t[nO]:0u) | (((q3>0.f)?w3t[nO+1]:0u)<<16);
                *(uint2*)&sh1u[(r0  )*LDA + sl] = make_uint2(e0, o0);
                *(uint2*)&sh1u[(r0+8)*LDA + sl] = make_uint2(e1, o1);
            }
#pragma unroll
        for (int mi=0;mi<2;mi++)
#pragma unroll
            for (int hi=0;hi<2;hi++){
                float v = qp[mi][hi];
                v += __shfl_xor_sync(0xffffffffu, v, 1);
                v += __shfl_xor_sync(0xffffffffu, v, 2);
                if (tg == 0) qps[wn*64 + wm*32 + mi*16 + g + 8*hi] = v;
            }
    }
    preloadB(Bpre, g_w2tpf, wn, g, sw, 0);
    __syncthreads();

    // ---- Phase C ----
#pragma unroll
    for (int mi=0;mi<2;mi++)
#pragma unroll
        for (int ni=0;ni<8;ni++)
#pragma unroll
            for (int j=0;j<4;j++) acc[mi][ni][j]=0.f;
    phase256(acc, sh1u, LDA, g_w2tpf, Bpre, wm, wn, g, tg);
    __syncthreads();
    {
#pragma unroll
        for (int mi=0;mi<2;mi++)
#pragma unroll
            for (int m2=0;m2<4;m2++){
                int niE = 2*m2, niO = niE+1;
                int r0 = wm*32 + mi*16 + g;
                int sl = fslot(wn*64 + niE*8 + 2*tg);
                int bE = (mi*8+niE)*4, bO = (mi*8+niO)*4;
                float p0 = ((mbits>>(bE+0))&1ull) ? acc[mi][niE][0] : 0.f;
                float p1 = ((mbits>>(bE+1))&1ull) ? acc[mi][niE][1] : 0.f;
                float p2 = ((mbits>>(bE+2))&1ull) ? acc[mi][niE][2] : 0.f;
                float p3 = ((mbits>>(bE+3))&1ull) ? acc[mi][niE][3] : 0.f;
                float q0 = ((mbits>>(bO+0))&1ull) ? acc[mi][niO][0] : 0.f;
                float q1 = ((mbits>>(bO+1))&1ull) ? acc[mi][niO][1] : 0.f;
                float q2 = ((mbits>>(bO+2))&1ull) ? acc[mi][niO][2] : 0.f;
                float q3 = ((mbits>>(bO+3))&1ull) ? acc[mi][niO][3] : 0.f;
                *(uint2*)&sh1u[(r0  )*LDA + sl] = make_uint2(pk(p0,p1), pk(q0,q1));
                *(uint2*)&sh1u[(r0+8)*LDA + sl] = make_uint2(pk(p2,p3), pk(q2,q3));
            }
    }
    __syncthreads();

    // ---- Phase D ----
    {
        const int wk  = wid >> 2;
        const int wm2 = wid & 3;
        float ad[2][4];
        ad[0][0]=ad[0][1]=ad[0][2]=ad[0][3]=0.f;
        ad[1][0]=ad[1][1]=ad[1][2]=ad[1][3]=0.f;
        int r0d = wm2*16 + g;
#pragma unroll
        for (int ks=0; ks<4; ks++){
            int c = wk*4 + ks;
            uint4 A0 = *(const uint4*)&sh1u[(r0d  )*LDA + c*16 + tg*4];
            uint4 A8 = *(const uint4*)&sh1u[(r0d+8)*LDA + c*16 + tg*4];
            unsigned ak0[4] = {A0.x, A8.x, A0.y, A8.y};
            unsigned ak1[4] = {A0.z, A8.z, A0.w, A8.w};
            uint4 B0 = __ldg((const uint4*)&g_w1atpf[c*256 + (g    )*16 + ((tg^(g&3))<<2)]);
            uint4 B1 = __ldg((const uint4*)&g_w1atpf[c*256 + (8 + g)*16 + ((tg^((8+g)&3))<<2)]);
            mma8h(ad[0], ak0, B0.x, B0.y);
            mma8h(ad[1], ak0, B1.x, B1.y);
            mma8h(ad[0], ak1, B0.z, B0.w);
            mma8h(ad[1], ak1, B1.z, B1.w);
        }
        __syncthreads();
#pragma unroll
        for (int nf=0;nf<2;nf++)
#pragma unroll
            for (int j=0;j<4;j++){
                int row = wm2*16 + g + 8*(j>>1);
                int col = nf*8 + 2*tg + (j&1);
                spf[wk*1024 + row*16 + col] = ad[nf][j];
            }
    }
    __syncthreads();

    // ================= fused SVGD =================
#pragma unroll
    for (int i=0;i<4;i++){
        int idx = i*NT + tid;
        Ss[idx] = spf[idx] + spf[1024+idx];
    }
    if (step == 2 && tid < ROWS){
        float q = qps[tid] + qps[64+tid] + qps[128+tid] + qps[192+tid] + b3[0];
        q_out[row0 + tid] = q;
    }
    hst[tid] = 0; hst[256 + tid] = 0;   // zero buf0 (both bsub halves)
    __syncthreads();

    const int t    = tid & 127;
    const int bsub = tid >> 7;
    const int pi   = t >> 2;
    const int jb   = (t & 3) * 8;
    const int jg   = t & 3;

    float Xi[DA];
#pragma unroll
    for (int d=0; d<DA; d++) Xi[d] = Xs[(bsub*32 + pi)*DA + d];
    float myd2[8];
    unsigned actm = 0;
#pragma unroll
    for (int jj=0; jj<8; jj++){
        int j = jb + jj;
        const float4* Xj = (const float4*)&Xs[(bsub*32 + j)*DA];
        float s = 0.f;
#pragma unroll
        for (int d4=0; d4<4; d4++){
            float4 xv = Xj[d4];
            float df0 = Xi[d4*4+0]-xv.x, df1 = Xi[d4*4+1]-xv.y;
            float df2 = Xi[d4*4+2]-xv.z, df3 = Xi[d4*4+3]-xv.w;
            s = fmaf(df0,df0,s); s = fmaf(df1,df1,s);
            s = fmaf(df2,df2,s); s = fmaf(df3,df3,s);
        }
        myd2[jj] = s;
        if (pi < j) actm |= 1u << jj;
    }

    // radix select: register rank/prefix, redundant per-warp scan, 1 sync/round
    int rrank = 239;
    unsigned prefix = 0u;
    unsigned pmask = 0u;
#pragma unroll 1
    for (int rd = 0; rd < 4; rd++){
        int shift = 24 - rd*8;
        int nb = (rd+1)&1;
        hst[nb*512 + tid] = 0;             // zero next buffer (both halves)
        hst[nb*512 + 256 + tid] = 0;
#pragma unroll
        for (int jj=0; jj<8; jj++){
            unsigned v = __float_as_uint(myd2[jj]);
            if (((actm>>jj)&1u) && (v & pmask) == prefix)
                atomicAdd(&hst[(rd&1)*512 + bsub*256 + ((v>>shift)&255)], 1u);
        }
        __syncthreads();
        {
            unsigned hv[8]; unsigned cnt = 0;
#pragma unroll
            for (int q=0;q<8;q++){ hv[q] = hst[(rd&1)*512 + bsub*256 + lane*8 + q]; cnt += hv[q]; }
            unsigned pref = cnt;
#pragma unroll
            for (int dd=1; dd<32; dd<<=1){
                unsigned vv = __shfl_up_sync(0xffffffffu, pref, dd);
                if (lane >= dd) pref += vv;
            }
            unsigned excl = pref - cnt;
            bool has = (excl <= (unsigned)rrank) && ((unsigned)rrank < excl + cnt);
            unsigned bal = __ballot_sync(0xffffffffu, has);
            int src = __ffs(bal) - 1;
            int bsel = 0, newr = 0;
            if (has){
                unsigned c2 = excl; bsel = lane*8;
#pragma unroll 1
                for (int q=0;q<8;q++){
                    if (c2 + hv[q] > (unsigned)rrank){ bsel = lane*8+q; break; }
                    c2 += hv[q];
                }
                newr = rrank - (int)c2;
            }
            bsel = __shfl_sync(0xffffffffu, bsel, src);
            newr = __shfl_sync(0xffffffffu, newr, src);
            rrank = newr;
            prefix |= ((unsigned)bsel) << shift;
        }
        pmask = 0xFFFFFFFFu << shift;
        __syncthreads();   // hist reads done before next round's accumulation
    }
    {
        const unsigned v1 = prefix;
        int cle = 0; unsigned mab = 0xFFFFFFFFu;
#pragma unroll
        for (int jj=0; jj<8; jj++){
            unsigned v = __float_as_uint(myd2[jj]);
            if ((actm>>jj)&1u){
                if (v <= v1) cle++;
                else mab = min(mab, v);
            }
        }
#pragma unroll
        for (int sh = 16; sh > 0; sh >>= 1){
            cle += __shfl_xor_sync(0xffffffffu, cle, sh);
            mab  = min(mab, __shfl_xor_sync(0xffffffffu, mab, sh));
        }
        if (lane == 0){ wcle[wid] = (unsigned)cle; wmin[wid] = mab; }
        __syncthreads();
        if (t == 0){
            unsigned tot = 0, m = 0xFFFFFFFFu;
            for (int w = 0; w < 4; w++){ tot += wcle[bsub*4+w]; m = min(m, wmin[bsub*4+w]); }
            unsigned s2 = (tot >= 241u) ? v1 : m;
            float med = 0.5f * (__uint_as_float(v1) + __uint_as_float(s2));
            float h = med / LN32 + 1e-8f;
            gam[bsub] = 1.f / (2.f * h);
        }
        __syncthreads();
    }

    {
        const float gamma = gam[bsub];
        const float tg2 = 2.f * gamma;
        float vd[DA];
#pragma unroll
        for (int d=0; d<DA; d++) vd[d] = 0.f;
        float t1 = 0.f, t2 = 0.f;
#pragma unroll 1
        for (int jj=0; jj<8; jj++){
            int j = jb + jj;
            float d2 = myd2[jj];
            float K = __expf(-gamma * d2);
            const float4* Xj = (const float4*)&Xs[(bsub*32 + j)*DA];
            const float4* Sj = (const float4*)&Ss[(bsub*32 + j)*DA];
            float dot = 0.f;
#pragma unroll
            for (int d4=0; d4<4; d4++){
                float4 xv = Xj[d4];
                float4 sv = Sj[d4];
                float df0 = Xi[d4*4+0]-xv.x, df1 = Xi[d4*4+1]-xv.y;
                float df2 = Xi[d4*4+2]-xv.z, df3 = Xi[d4*4+3]-xv.w;
                dot = fmaf(df0, sv.x, dot); dot = fmaf(df1, sv.y, dot);
                dot = fmaf(df2, sv.z, dot); dot = fmaf(df3, sv.w, dot);
                vd[d4*4+0] += K * fmaf(tg2, df0, sv.x);
                vd[d4*4+1] += K * fmaf(tg2, df1, sv.y);
                vd[d4*4+2] += K * fmaf(tg2, df2, sv.z);
                vd[d4*4+3] += K * fmaf(tg2, df3, sv.w);
            }
            t1 += -tg2 * K * dot;
            t2 += fmaf(tg2 * d2, K, -16.f * K);
        }
#pragma unroll
        for (int d=0; d<DA; d++){
            vd[d] += __shfl_xor_sync(0xffffffffu, vd[d], 1);
            vd[d] += __shfl_xor_sync(0xffffffffu, vd[d], 2);
        }
        t1 += __shfl_xor_sync(0xffffffffu, t1, 1);
        t1 += __shfl_xor_sync(0xffffffffu, t1, 2);
        t2 += __shfl_xor_sync(0xffffffffu, t2, 1);
        t2 += __shfl_xor_sync(0xffffffffu, t2, 2);

        int lrow = bsub*32 + pi;
        int grow = row0 + lrow;
        __syncthreads();   // all Xs/Ss reads complete before in-place update
        if (jg == 0){
            float tmp1 = t1 * (1.f/NN);
            float tmp2 = -tg2 * t2 * (1.f/NN);
            float lp = lgp[lrow] - LR * (tmp1 + tmp2);
            lgp[lrow] = lp;
            if (step == 2) out_logp[grow] = lp;
        }
#pragma unroll
        for (int dd=0; dd<4; dd++){
            int d = jg*4 + dd;
            float av = Xi[d] + LR * (vd[d] * (1.f/NN));
            av = fminf(fmaxf(av, -1.f), 1.f);
            Xs[lrow*DA + d] = av;
            if (step == 2) out_a[(size_t)grow*DA + d] = av;
        }
    }
    __syncthreads();   // Xs updates visible before next step's pack

    } // step loop
}

// ---------------- launch ----------------
extern "C" void kernel_launch(void* const* d_in, const int* in_sizes, int n_in,
                              void* d_out, int out_size)
{
    const float* obs = (const float*)d_in[0];
    const float* a   = (const float*)d_in[1];
    const float* w1  = (const float*)d_in[2];
    const float* b1  = (const float*)d_in[3];
    const float* w2  = (const float*)d_in[4];
    const float* b2  = (const float*)d_in[5];
    const float* w3  = (const float*)d_in[6];
    const float* b3  = (const float*)d_in[7];

    float* out      = (float*)d_out;
    float* out_a    = out;
    float* out_logp = out + BN*DA;
    float* out_q    = out + BN*DA + BN;

    cudaFuncSetAttribute(mlp_kernel,  cudaFuncAttributeMaxDynamicSharedMemorySize, MLP_SMEM);
    cudaFuncSetAttribute(pre1_kernel, cudaFuncAttributeMaxDynamicSharedMemorySize, PRE1_SMEM);

    pack_weights<<<156, 512>>>(w1, w2);
    pre1_kernel<<<BN/ROWS, NT, PRE1_SMEM>>>(obs, b1);
    mlp_kernel<<<BN/ROWS, NT, MLP_SMEM>>>(a, b2, w3, b3, out_q, out_a, out_logp);
}

// round 16
// speedup vs baseline: 1.1418x; 1.1418x over previous
#include <cuda_runtime.h>
#include <cuda_fp16.h>
#include <math.h>

#define BB   4096
#define NN   32
#define DA   16
#define DOBS 64
#define HH   256
#define BN   (BB*NN)
#define ROWS 64
#define NT   256
#define LDA  144
#define LN32 3.4657359027997265f
#define LR   0.1f

// ---------------- device scratch ----------------
__device__ float    g_pre1[BN*HH];     // fragment-contiguous, pre-biased with b1
__device__ unsigned g_w2pf [8*4096];
__device__ unsigned g_w2tpf[8*4096];
__device__ unsigned g_w1pf [2*4096];
__device__ unsigned g_w1apf[  4096];
__device__ unsigned g_w1atpf[ 2048];

// ---------------- helpers ----------------
__device__ __forceinline__ unsigned pk(float lo, float hi){
    __half2 h = __floats2half2_rn(lo, hi);
    return *reinterpret_cast<unsigned*>(&h);
}
__device__ __forceinline__ void mma8h(float* c, const unsigned* a, unsigned b0, unsigned b1){
    asm volatile("mma.sync.aligned.m16n8k16.row.col.f32.f16.f16.f32 "
                 "{%0,%1,%2,%3},{%4,%5,%6,%7},{%8,%9},{%0,%1,%2,%3};\n"
                 : "+f"(c[0]),"+f"(c[1]),"+f"(c[2]),"+f"(c[3])
                 : "r"(a[0]),"r"(a[1]),"r"(a[2]),"r"(a[3]),"r"(b0),"r"(b1));
}
__device__ __forceinline__ int fslot(int n){
    return ((n>>5)<<4) | (((n>>1)&3)<<2) | ((n>>3)&1) | (((n>>4)&1)<<1);
}
__device__ __forceinline__ void preloadB(uint4 B[4], const unsigned* __restrict__ img,
                                         int wn, int g, int sw, int h){
#pragma unroll
    for (int ni=0;ni<4;ni++){
        int n = wn*64 + (h*4+ni)*8 + g;
        B[ni] = __ldg((const uint4*)&img[n*16 + sw]);
    }
}
// pipelined 256-K phase (R13 interleaved order)
__device__ __forceinline__ void phase256(float acc[2][8][4], const unsigned* A, int lda,
                                         const unsigned* __restrict__ img, uint4 B[4],
                                         int wm, int wn, int g, int tg)
{
    const int sw = ((tg ^ (g&3))<<2);
    const int r0 = wm*32 + g;
    unsigned a0k0[4], a0k1[4], a1k0[4], a1k1[4];
#pragma unroll
    for (int step=0; step<16; step++){
        const int c = step>>1, h = step&1;
        uint4 Bn[4];
        if (step<15)
            preloadB(Bn, img + ((step+1)>>1)*4096, wn, g, sw, (step+1)&1);
        if (h==0){
            const int ab = c*16 + tg*4;
            uint4 A0 = *(const uint4*)&A[(r0   )*lda + ab];
            uint4 A8 = *(const uint4*)&A[(r0+ 8)*lda + ab];
            uint4 A16= *(const uint4*)&A[(r0+16)*lda + ab];
            uint4 A24= *(const uint4*)&A[(r0+24)*lda + ab];
            a0k0[0]=A0.x; a0k0[1]=A8.x; a0k0[2]=A0.y; a0k0[3]=A8.y;
            a0k1[0]=A0.z; a0k1[1]=A8.z; a0k1[2]=A0.w; a0k1[3]=A8.w;
            a1k0[0]=A16.x; a1k0[1]=A24.x; a1k0[2]=A16.y; a1k0[3]=A24.y;
            a1k1[0]=A16.z; a1k1[1]=A24.z; a1k1[2]=A16.w; a1k1[3]=A24.w;
        }
#pragma unroll
        for (int ni=0;ni<4;ni++){
            int no = h*4+ni;
            mma8h(acc[0][no], a0k0, B[ni].x, B[ni].y);
            mma8h(acc[1][no], a1k0, B[ni].x, B[ni].y);
            mma8h(acc[0][no], a0k1, B[ni].z, B[ni].w);
            mma8h(acc[1][no], a1k1, B[ni].z, B[ni].w);
        }
        if (step<15){
#pragma unroll
            for (int ni=0;ni<4;ni++) B[ni]=Bn[ni];
        }
    }
}
__device__ __forceinline__ void mma_32k(float acc[2][8][4], const unsigned* A, int lda, int c,
                                        const unsigned* __restrict__ gslab, int wm, int wn, int g, int tg)
{
    const int r0 = wm*32 + g;
    const int ab = c*16 + tg*4;
    uint4 A0 = *(const uint4*)&A[(r0   )*lda + ab];
    uint4 A8 = *(const uint4*)&A[(r0+ 8)*lda + ab];
    uint4 A16= *(const uint4*)&A[(r0+16)*lda + ab];
    uint4 A24= *(const uint4*)&A[(r0+24)*lda + ab];
    unsigned a0k0[4] = {A0.x, A8.x, A0.y, A8.y};
    unsigned a0k1[4] = {A0.z, A8.z, A0.w, A8.w};
    unsigned a1k0[4] = {A16.x, A24.x, A16.y, A24.y};
    unsigned a1k1[4] = {A16.z, A24.z, A16.w, A24.w};
    const int sw = ((tg ^ (g&3))<<2);
#pragma unroll
    for (int ni=0;ni<8;ni++){
        int n = wn*64 + ni*8 + g;
        uint4 B = __ldg((const uint4*)&gslab[n*16 + sw]);
        mma8h(acc[0][ni], a0k0, B.x, B.y);
        mma8h(acc[1][ni], a1k0, B.x, B.y);
        mma8h(acc[0][ni], a0k1, B.z, B.w);
        mma8h(acc[1][ni], a1k1, B.z, B.w);
    }
}

// ---------------- one-time weight packing ----------------
__global__ void pack_weights(const float* __restrict__ w1, const float* __restrict__ w2)
{
    int idx = blockIdx.x * 512 + threadIdx.x;
    if (idx < 32768){
        int c = idx>>12, off = idx&4095, n = off>>4, rem = off&15;
        int tg = (rem>>2) ^ (n&3), j = rem&3;
        int k0 = c*32 + 2*tg + (j&1)*8 + ((j>>1)&1)*16;
        g_w2pf[idx] = pk(w2[(size_t)k0*HH+n], w2[(size_t)(k0+1)*HH+n]);
    } else if (idx < 65536){
        int t = idx-32768;
        int c = t>>12, off = t&4095, n = off>>4, rem = off&15;
        int tg = (rem>>2) ^ (n&3), j = rem&3;
        int k0 = c*32 + 2*tg + (j&1)*8 + ((j>>1)&1)*16;
        g_w2tpf[t] = pk(w2[(size_t)n*HH+k0], w2[(size_t)n*HH+k0+1]);
    } else if (idx < 73728){
        int t = idx-65536;
        int c = t>>12, off = t&4095, n = off>>4, rem = off&15;
        int tg = (rem>>2) ^ (n&3), j = rem&3;
        int k0 = c*32 + 2*tg + (j&1)*8 + ((j>>1)&1)*16;
        g_w1pf[t] = pk(w1[(size_t)k0*HH+n], w1[(size_t)(k0+1)*HH+n]);
    } else if (idx < 77824){
        int t = idx-73728;
        int n = t>>4, rem = t&15;
        int tg = (rem>>2) ^ (n&3), j = rem&3;
        int k0 = 2*tg + (j&1)*8 + ((j>>1)&1)*16;
        g_w1apf[t] = (k0 < 16) ? pk(w1[(size_t)(DOBS+k0)*HH+n], w1[(size_t)(DOBS+k0+1)*HH+n]) : 0u;
    } else if (idx < 79872){
        int t = idx-77824;
        int c = t>>8, r = t&255, n = r>>4, rem = r&15;
        int tg = (rem>>2) ^ (n&3), j = rem&3;
        int k0 = c*32 + 2*tg + (j&1)*8 + ((j>>1)&1)*16;
        g_w1atpf[t] = pk(w1[(size_t)(DOBS+n)*HH+k0], w1[(size_t)(DOBS+n)*HH+k0+1]);
    }
}

// ---------------- pre1 = obs @ W1[0:64,:] + b1 ----------------
#define PRE1_SMEM ((2304 + 256) * 4)
__global__ void __launch_bounds__(NT) pre1_kernel(const float* __restrict__ obs,
                                                  const float* __restrict__ b1)
{
    extern __shared__ unsigned smu[];
    unsigned* obs_s = smu;
    float*    b1s   = (float*)(smu + 2304);
    const int tid = threadIdx.x;
    const int lane = tid & 31, wid = tid >> 5;
    const int g = lane >> 2, tg = lane & 3;
    const int wm = wid >> 2, wn = wid & 3;
    const int row0 = blockIdx.x * ROWS;

    b1s[tid] = b1[tid];
#pragma unroll
    for (int i=0;i<8;i++){
        int lin = i*NT + tid; int r = lin>>5, s = lin&31;
        int c = s>>4, rem = s&15, t = rem>>2, j = rem&3;
        int k0 = c*32 + 2*t + (j&1)*8 + ((j>>1)&1)*16;
        const float* orow = &obs[(size_t)(row0 + r)*DOBS];
        obs_s[r*36 + s] = pk(orow[k0], orow[k0+1]);
    }
    __syncthreads();

    float acc[2][8][4];
#pragma unroll
    for (int mi=0;mi<2;mi++)
#pragma unroll
        for (int ni=0;ni<8;ni++)
#pragma unroll
            for (int j=0;j<4;j++) acc[mi][ni][j]=0.f;
#pragma unroll
    for (int s=0;s<2;s++)
        mma_32k(acc, obs_s, 36, s, g_w1pf + s*4096, wm, wn, g, tg);

    float4* pp = (float4*)(g_pre1 + ((size_t)blockIdx.x*NT + tid)*64);
#pragma unroll
    for (int mi=0;mi<2;mi++)
#pragma unroll
        for (int ni=0;ni<8;ni++){
            int n = wn*64 + ni*8 + 2*tg;
            pp[mi*8+ni] = make_float4(acc[mi][ni][0]+b1s[n], acc[mi][ni][1]+b1s[n+1],
                                      acc[mi][ni][2]+b1s[n], acc[mi][ni][3]+b1s[n+1]);
        }
}

// ---------------- fused 3-step MLP + SVGD ----------------
#define OFF_H1   0
#define OFF_AUX  9216
#define OFF_SS   11264
#define OFF_QP   12288
#define OFF_XS   12544
#define OFF_LGP  13568
#define OFF_PB2  13824
#define OFF_W3R  14080
#define OFF_W3T  14336
#define OFF_HIST 14592
#define MLP_SMEM (15712*4)

__global__ void __launch_bounds__(NT,2) mlp_kernel(
    const float* __restrict__ a_in, const float* __restrict__ b2,
    const float* __restrict__ w3, const float* __restrict__ b3,
    float* __restrict__ q_out, float* __restrict__ out_a, float* __restrict__ out_logp)
{
    extern __shared__ unsigned smu[];
    unsigned* sh1u = smu + OFF_H1;
    unsigned* asu  = smu + OFF_AUX;
    float*    spf  = (float*)(smu + OFF_AUX);
    float*    Ss   = (float*)(smu + OFF_SS);
    float*    qps  = (float*)(smu + OFF_QP);
    float*    Xs   = (float*)(smu + OFF_XS);
    float*    lgp  = (float*)(smu + OFF_LGP);
    float*    b2s  = (float*)(smu + OFF_PB2);
    float*    w3r  = (float*)(smu + OFF_W3R);
    unsigned* w3t  = smu + OFF_W3T;
    unsigned* hst  = smu + OFF_HIST;                 // 2 bufs x (2 bsub x 256)
    unsigned* wcle = smu + OFF_HIST + 1024;
    unsigned* wmin = smu + OFF_HIST + 1032;
    float*    gam  = (float*)(smu + OFF_HIST + 1040);

    const int tid = threadIdx.x;
    const int lane = tid & 31, wid = tid >> 5;
    const int g = lane >> 2, tg = lane & 3;
    const int wm = wid >> 2, wn = wid & 3;
    const int sw = ((tg ^ (g&3))<<2);
    const int row0 = blockIdx.x * ROWS;

    // ---- stage once ----
    {
        float4 av = *(const float4*)&a_in[(size_t)row0*DA + tid*4];
        *(float4*)&Xs[tid*4] = av;
        b2s[tid] = b2[tid];
        float v = w3[tid]; w3r[tid] = v;
        w3t[tid] = (unsigned)__half_as_ushort(__float2half_rn(v));
        if (tid < ROWS) lgp[tid] = 0.f;
    }
    __syncthreads();

#pragma unroll 1
    for (int step = 0; step < 3; step++){

    // pack actions fp16 pairs
#pragma unroll
    for (int i=0;i<4;i++){
        int lin = i*NT + tid; int r = lin>>4, s = lin&15;
        int t = s>>2, j = s&3;
        unsigned v = 0u;
        if (j < 2){
            int k0 = 2*t + (j&1)*8;
            v = pk(Xs[r*DA + k0], Xs[r*DA + k0 + 1]);
        }
        asu[r*16 + s] = v;
    }
    __syncthreads();

    float acc[2][8][4];

    // ---- Phase A: h1 = relu(pre1b + a@W1a) ----
    {
        const float4* pp = (const float4*)(g_pre1 + ((size_t)blockIdx.x*NT + tid)*64);
#pragma unroll
        for (int mi=0;mi<2;mi++)
#pragma unroll
            for (int ni=0;ni<8;ni++){
                float4 v = pp[mi*8+ni];
                acc[mi][ni][0]=v.x; acc[mi][ni][1]=v.y; acc[mi][ni][2]=v.z; acc[mi][ni][3]=v.w;
            }
        mma_32k(acc, asu, 16, 0, g_w1apf, wm, wn, g, tg);
    }
    unsigned long long mbits = 0ull;
    {
#pragma unroll
        for (int mi=0;mi<2;mi++)
#pragma unroll
            for (int m2=0;m2<4;m2++){
                int niE = 2*m2, niO = niE+1;
                int nE = wn*64 + niE*8 + 2*tg;
                int r0 = wm*32 + mi*16 + g;
                int sl = fslot(nE);
                float p0 = acc[mi][niE][0];
                float p1 = acc[mi][niE][1];
                float p2 = acc[mi][niE][2];
                float p3 = acc[mi][niE][3];
                float q0 = acc[mi][niO][0];
                float q1 = acc[mi][niO][1];
                float q2 = acc[mi][niO][2];
                float q3 = acc[mi][niO][3];
                int bE = (mi*8+niE)*4, bO = (mi*8+niO)*4;
                mbits |= ((unsigned long long)(p0>0.f))<<(bE+0);
                mbits |= ((unsigned long long)(p1>0.f))<<(bE+1);
                mbits |= ((unsigned long long)(p2>0.f))<<(bE+2);
                mbits |= ((unsigned long long)(p3>0.f))<<(bE+3);
                mbits |= ((unsigned long long)(q0>0.f))<<(bO+0);
                mbits |= ((unsigned long long)(q1>0.f))<<(bO+1);
                mbits |= ((unsigned long long)(q2>0.f))<<(bO+2);
                mbits |= ((unsigned long long)(q3>0.f))<<(bO+3);
                *(uint2*)&sh1u[(r0  )*LDA + sl] =
                    make_uint2(pk(fmaxf(p0,0.f),fmaxf(p1,0.f)), pk(fmaxf(q0,0.f),fmaxf(q1,0.f)));
                *(uint2*)&sh1u[(r0+8)*LDA + sl] =
                    make_uint2(pk(fmaxf(p2,0.f),fmaxf(p3,0.f)), pk(fmaxf(q2,0.f),fmaxf(q3,0.f)));
            }
    }
    uint4 Bpre[4];
    preloadB(Bpre, g_w2pf, wn, g, sw, 0);
    __syncthreads();

    // ---- Phase B ----
#pragma unroll
    for (int mi=0;mi<2;mi++)
#pragma unroll
        for (int ni=0;ni<8;ni++)
#pragma unroll
            for (int j=0;j<4;j++) acc[mi][ni][j]=0.f;
    phase256(acc, sh1u, LDA, g_w2pf, Bpre, wm, wn, g, tg);
    __syncthreads();
    {
        float qp[2][2] = {{0.f,0.f},{0.f,0.f}};
        const bool doq = (step == 2);
#pragma unroll
        for (int mi=0;mi<2;mi++)
#pragma unroll
            for (int m2=0;m2<4;m2++){
                int niE = 2*m2, niO = niE+1;
                int nE = wn*64 + niE*8 + 2*tg;
                int nO = nE + 8;
                int r0 = wm*32 + mi*16 + g;
                int sl = fslot(nE);
                float p0 = acc[mi][niE][0] + b2s[nE];
                float p1 = acc[mi][niE][1] + b2s[nE+1];
                float p2 = acc[mi][niE][2] + b2s[nE];
                float p3 = acc[mi][niE][3] + b2s[nE+1];
                float q0 = acc[mi][niO][0] + b2s[nO];
                float q1 = acc[mi][niO][1] + b2s[nO+1];
                float q2 = acc[mi][niO][2] + b2s[nO];
                float q3 = acc[mi][niO][3] + b2s[nO+1];
                if (doq){
                    qp[mi][0] += fmaxf(p0,0.f)*w3r[nE] + fmaxf(p1,0.f)*w3r[nE+1]
                               + fmaxf(q0,0.f)*w3r[nO] + fmaxf(q1,0.f)*w3r[nO+1];
                    qp[mi][1] += fmaxf(p2,0.f)*w3r[nE] + fmaxf(p3,0.f)*w3r[nE+1]
                               + fmaxf(q2,0.f)*w3r[nO] + fmaxf(q3,0.f)*w3r[nO+1];
                }
                unsigned e0 = ((p0>0.f)?w3t[nE]:0u) | (((p1>0.f)?w3t[nE+1]:0u)<<16);
                unsigned o0 = ((q0>0.f)?w3t[nO]:0u) | (((q1>0.f)?w3t[nO+1]:0u)<<16);
                unsigned e1 = ((p2>0.f)?w3t[nE]:0u) | (((p3>0.f)?w3t[nE+1]:0u)<<16);
                unsigned o1 = ((q2>0.f)?w3t[nO]:0u) | (((q3>0.f)?w3t[nO+1]:0u)<<16);
                *(uint2*)&sh1u[(r0  )*LDA + sl] = make_uint2(e0, o0);
                *(uint2*)&sh1u[(r0+8)*LDA + sl] = make_uint2(e1, o1);
            }
        if (doq){
#pragma unroll
            for (int mi=0;mi<2;mi++)
#pragma unroll
                for (int hi=0;hi<2;hi++){
                    float v = qp[mi][hi];
                    v += __shfl_xor_sync(0xffffffffu, v, 1);
                    v += __shfl_xor_sync(0xffffffffu, v, 2);
                    if (tg == 0) qps[wn*64 + wm*32 + mi*16 + g + 8*hi] = v;
                }
        }
    }
    preloadB(Bpre, g_w2tpf, wn, g, sw, 0);
    __syncthreads();

    // ---- Phase C ----
#pragma unroll
    for (int mi=0;mi<2;mi++)
#pragma unroll
        for (int ni=0;ni<8;ni++)
#pragma unroll
            for (int j=0;j<4;j++) acc[mi][ni][j]=0.f;
    phase256(acc, sh1u, LDA, g_w2tpf, Bpre, wm, wn, g, tg);
    __syncthreads();
    {
#pragma unroll
        for (int mi=0;mi<2;mi++)
#pragma unroll
            for (int m2=0;m2<4;m2++){
                int niE = 2*m2, niO = niE+1;
                int r0 = wm*32 + mi*16 + g;
                int sl = fslot(wn*64 + niE*8 + 2*tg);
                int bE = (mi*8+niE)*4, bO = (mi*8+niO)*4;
                float p0 = ((mbits>>(bE+0))&1ull) ? acc[mi][niE][0] : 0.f;
                float p1 = ((mbits>>(bE+1))&1ull) ? acc[mi][niE][1] : 0.f;
                float p2 = ((mbits>>(bE+2))&1ull) ? acc[mi][niE][2] : 0.f;
                float p3 = ((mbits>>(bE+3))&1ull) ? acc[mi][niE][3] : 0.f;
                float q0 = ((mbits>>(bO+0))&1ull) ? acc[mi][niO][0] : 0.f;
                float q1 = ((mbits>>(bO+1))&1ull) ? acc[mi][niO][1] : 0.f;
                float q2 = ((mbits>>(bO+2))&1ull) ? acc[mi][niO][2] : 0.f;
                float q3 = ((mbits>>(bO+3))&1ull) ? acc[mi][niO][3] : 0.f;
                *(uint2*)&sh1u[(r0  )*LDA + sl] = make_uint2(pk(p0,p1), pk(q0,q1));
                *(uint2*)&sh1u[(r0+8)*LDA + sl] = make_uint2(pk(p2,p3), pk(q2,q3));
            }
    }
    __syncthreads();

    // ---- Phase D ----
    {
        const int wk  = wid >> 2;
        const int wm2 = wid & 3;
        float ad[2][4];
        ad[0][0]=ad[0][1]=ad[0][2]=ad[0][3]=0.f;
        ad[1][0]=ad[1][1]=ad[1][2]=ad[1][3]=0.f;
        int r0d = wm2*16 + g;
#pragma unroll
        for (int ks=0; ks<4; ks++){
            int c = wk*4 + ks;
            uint4 A0 = *(const uint4*)&sh1u[(r0d  )*LDA + c*16 + tg*4];
            uint4 A8 = *(const uint4*)&sh1u[(r0d+8)*LDA + c*16 + tg*4];
            unsigned ak0[4] = {A0.x, A8.x, A0.y, A8.y};
            unsigned ak1[4] = {A0.z, A8.z, A0.w, A8.w};
            uint4 B0 = __ldg((const uint4*)&g_w1atpf[c*256 + (g    )*16 + ((tg^(g&3))<<2)]);
            uint4 B1 = __ldg((const uint4*)&g_w1atpf[c*256 + (8 + g)*16 + ((tg^((8+g)&3))<<2)]);
            mma8h(ad[0], ak0, B0.x, B0.y);
            mma8h(ad[1], ak0, B1.x, B1.y);
            mma8h(ad[0], ak1, B0.z, B0.w);
            mma8h(ad[1], ak1, B1.z, B1.w);
        }
        __syncthreads();
#pragma unroll
        for (int nf=0;nf<2;nf++)
#pragma unroll
            for (int j=0;j<4;j++){
                int row = wm2*16 + g + 8*(j>>1);
                int col = nf*8 + 2*tg + (j&1);
                spf[wk*1024 + row*16 + col] = ad[nf][j];
            }
    }
    __syncthreads();

    // ================= fused SVGD =================
#pragma unroll
    for (int i=0;i<4;i++){
        int idx = i*NT + tid;
        Ss[idx] = spf[idx] + spf[1024+idx];
    }
    if (step == 2 && tid < ROWS){
        float q = qps[tid] + qps[64+tid] + qps[128+tid] + qps[192+tid] + b3[0];
        q_out[row0 + tid] = q;
    }
    hst[tid] = 0; hst[256 + tid] = 0;   // zero buf0 (both bsub halves)
    __syncthreads();

    const int t    = tid & 127;
    const int bsub = tid >> 7;
    const int pi   = t >> 2;
    const int jb   = (t & 3) * 8;
    const int jg   = t & 3;

    float Xi[DA];
#pragma unroll
    for (int d=0; d<DA; d++) Xi[d] = Xs[(bsub*32 + pi)*DA + d];
    float myd2[8];
    unsigned actm = 0;
#pragma unroll
    for (int jj=0; jj<8; jj++){
        int j = jb + jj;
        const float4* Xj = (const float4*)&Xs[(bsub*32 + j)*DA];
        float s = 0.f;
#pragma unroll
        for (int d4=0; d4<4; d4++){
            float4 xv = Xj[d4];
            float df0 = Xi[d4*4+0]-xv.x, df1 = Xi[d4*4+1]-xv.y;
            float df2 = Xi[d4*4+2]-xv.z, df3 = Xi[d4*4+3]-xv.w;
            s = fmaf(df0,df0,s); s = fmaf(df1,df1,s);
            s = fmaf(df2,df2,s); s = fmaf(df3,df3,s);
        }
        myd2[jj] = s;
        if (pi < j) actm |= 1u << jj;
    }

    // radix select: register rank/prefix, redundant per-warp scan, 1 sync/round
    int rrank = 239;
    unsigned prefix = 0u;
    unsigned pmask = 0u;
#pragma unroll 1
    for (int rd = 0; rd < 4; rd++){
        int shift = 24 - rd*8;
        int nb = (rd+1)&1;
        hst[nb*512 + tid] = 0;             // zero next buffer (both halves)
        hst[nb*512 + 256 + tid] = 0;
#pragma unroll
        for (int jj=0; jj<8; jj++){
            unsigned v = __float_as_uint(myd2[jj]);
            if (((actm>>jj)&1u) && (v & pmask) == prefix)
                atomicAdd(&hst[(rd&1)*512 + bsub*256 + ((v>>shift)&255)], 1u);
        }
        __syncthreads();
        {
            unsigned hv[8]; unsigned cnt = 0;
#pragma unroll
            for (int q=0;q<8;q++){ hv[q] = hst[(rd&1)*512 + bsub*256 + lane*8 + q]; cnt += hv[q]; }
            unsigned pref = cnt;
#pragma unroll
            for (int dd=1; dd<32; dd<<=1){
                unsigned vv = __shfl_up_sync(0xffffffffu, pref, dd);
                if (lane >= dd) pref += vv;
            }
            unsigned excl = pref - cnt;
            bool has = (excl <= (unsigned)rrank) && ((unsigned)rrank < excl + cnt);
            unsigned bal = __ballot_sync(0xffffffffu, has);
            int src = __ffs(bal) - 1;
            int bsel = 0, newr = 0;
            if (has){
                unsigned c2 = excl; bsel = lane*8;
#pragma unroll 1
                for (int q=0;q<8;q++){
                    if (c2 + hv[q] > (unsigned)rrank){ bsel = lane*8+q; break; }
                    c2 += hv[q];
                }
                newr = rrank - (int)c2;
            }
            bsel = __shfl_sync(0xffffffffu, bsel, src);
            newr = __shfl_sync(0xffffffffu, newr, src);
            rrank = newr;
            prefix |= ((unsigned)bsel) << shift;
        }
        pmask = 0xFFFFFFFFu << shift;
        __syncthreads();   // hist reads done before next round's accumulation
    }
    {
        const unsigned v1 = prefix;
        int cle = 0; unsigned mab = 0xFFFFFFFFu;
#pragma unroll
        for (int jj=0; jj<8; jj++){
            unsigned v = __float_as_uint(myd2[jj]);
            if ((actm>>jj)&1u){
                if (v <= v1) cle++;
                else mab = min(mab, v);
            }
        }
#pragma unroll
        for (int sh = 16; sh > 0; sh >>= 1){
            cle += __shfl_xor_sync(0xffffffffu, cle, sh);
            mab  = min(mab, __shfl_xor_sync(0xffffffffu, mab, sh));
        }
        if (lane == 0){ wcle[wid] = (unsigned)cle; wmin[wid] = mab; }
        __syncthreads();
        if (t == 0){
            unsigned tot = 0, m = 0xFFFFFFFFu;
            for (int w = 0; w < 4; w++){ tot += wcle[bsub*4+w]; m = min(m, wmin[bsub*4+w]); }
            unsigned s2 = (tot >= 241u) ? v1 : m;
            float med = 0.5f * (__uint_as_float(v1) + __uint_as_float(s2));
            float h = med / LN32 + 1e-8f;
            gam[bsub] = 1.f / (2.f * h);
        }
        __syncthreads();
    }

    {
        const float gamma = gam[bsub];
        const float tg2 = 2.f * gamma;
        float vd[DA];
#pragma unroll
        for (int d=0; d<DA; d++) vd[d] = 0.f;
        float t1 = 0.f, t2 = 0.f;
#pragma unroll 1
        for (int jj=0; jj<8; jj++){
            int j = jb + jj;
            float d2 = myd2[jj];
            float K = __expf(-gamma * d2);
            const float4* Xj = (const float4*)&Xs[(bsub*32 + j)*DA];
            const float4* Sj = (const float4*)&Ss[(bsub*32 + j)*DA];
            float dot = 0.f;
#pragma unroll
            for (int d4=0; d4<4; d4++){
                float4 xv = Xj[d4];
                float4 sv = Sj[d4];
                float df0 = Xi[d4*4+0]-xv.x, df1 = Xi[d4*4+1]-xv.y;
                float df2 = Xi[d4*4+2]-xv.z, df3 = Xi[d4*4+3]-xv.w;
                dot = fmaf(df0, sv.x, dot); dot = fmaf(df1, sv.y, dot);
                dot = fmaf(df2, sv.z, dot); dot = fmaf(df3, sv.w, dot);
                vd[d4*4+0] += K * fmaf(tg2, df0, sv.x);
                vd[d4*4+1] += K * fmaf(tg2, df1, sv.y);
                vd[d4*4+2] += K * fmaf(tg2, df2, sv.z);
                vd[d4*4+3] += K * fmaf(tg2, df3, sv.w);
            }
            t1 += -tg2 * K * dot;
            t2 += fmaf(tg2 * d2, K, -16.f * K);
        }
#pragma unroll
        for (int d=0; d<DA; d++){
            vd[d] += __shfl_xor_sync(0xffffffffu, vd[d], 1);
            vd[d] += __shfl_xor_sync(0xffffffffu, vd[d], 2);
        }
        t1 += __shfl_xor_sync(0xffffffffu, t1, 1);
        t1 += __shfl_xor_sync(0xffffffffu, t1, 2);
        t2 += __shfl_xor_sync(0xffffffffu, t2, 1);
        t2 += __shfl_xor_sync(0xffffffffu, t2, 2);

        int lrow = bsub*32 + pi;
        int grow = row0 + lrow;
        __syncthreads();   // all Xs/Ss reads complete before in-place update
        if (jg == 0){
            float tmp1 = t1 * (1.f/NN);
            float tmp2 = -tg2 * t2 * (1.f/NN);
            float lp = lgp[lrow] - LR * (tmp1 + tmp2);
            lgp[lrow] = lp;
            if (step == 2) out_logp[grow] = lp;
        }
#pragma unroll
        for (int dd=0; dd<4; dd++){
            int d = jg*4 + dd;
            float av = Xi[d] + LR * (vd[d] * (1.f/NN));
            av = fminf(fmaxf(av, -1.f), 1.f);
            Xs[lrow*DA + d] = av;
            if (step == 2) out_a[(size_t)grow*DA + d] = av;
        }
    }
    __syncthreads();   // Xs updates visible before next step's pack

    } // step loop
}

// ---------------- launch ----------------
extern "C" void kernel_launch(void* const* d_in, const int* in_sizes, int n_in,
                              void* d_out, int out_size)
{
    const float* obs = (const float*)d_in[0];
    const float* a   = (const float*)d_in[1];
    const float* w1  = (const float*)d_in[2];
    const float* b1  = (const float*)d_in[3];
    const float* w2  = (const float*)d_in[4];
    const float* b2  = (const float*)d_in[5];
    const float* w3  = (const float*)d_in[6];
    const float* b3  = (const float*)d_in[7];

    float* out      = (float*)d_out;
    float* out_a    = out;
    float* out_logp = out + BN*DA;
    float* out_q    = out + BN*DA + BN;

    cudaFuncSetAttribute(mlp_kernel,  cudaFuncAttributeMaxDynamicSharedMemorySize, MLP_SMEM);
    cudaFuncSetAttribute(pre1_kernel, cudaFuncAttributeMaxDynamicSharedMemorySize, PRE1_SMEM);

    pack_weights<<<156, 512>>>(w1, w2);
    pre1_kernel<<<BN/ROWS, NT, PRE1_SMEM>>>(obs, b1);
    mlp_kernel<<<BN/ROWS, NT, MLP_SMEM>>>(a, b2, w3, b3, out_q, out_a, out_logp);
}